// round 8
// baseline (speedup 1.0000x reference)
#include <cuda_runtime.h>
#include <math.h>

#define NCLS 97
#define LOG2E 1.4426950408889634f
#define NBLK 456   // 152 SMs x 3 resident blocks -> single wave

// Final-accumulation state. Zero-initialized at module load; last block of each
// launch resets it, so graph replays always start from zero.
__device__ double   g_sum;
__device__ unsigned g_count;

__device__ __forceinline__ float ex2a(float x) {
    float y;
    asm("ex2.approx.ftz.f32 %0, %1;" : "=f"(y) : "f"(x));
    return y;   // ex2a(-INF) == 0
}

struct Seg {
    float a[8], b[8], c[8];          // cols lane, lane+32, lane+64 of rows 0..7
    float lab0, lab1, lab2, lab96;   // labels at the lane's column slots
    float row0, r96;                 // aux: lane-owned row's col 0 / col 96
    int   len;
};

__device__ __forceinline__ void load_seg(Seg& S,
                                         const float* __restrict__ logits,
                                         const float* __restrict__ labels,
                                         const int*   __restrict__ pos,
                                         int e, int lane)
{
    const int st  = pos[2 * e];
    const int len = pos[2 * e + 1] - st;            // == 8 for this data
    S.len = len;
    const float* seg = logits + (size_t)st * NCLS;
    const float* lab = labels + (size_t)e  * NCLS;

    S.lab0  = lab[lane];
    S.lab1  = lab[lane + 32];
    S.lab2  = lab[lane + 64];
    S.lab96 = lab[96];

    const bool aux = (lane < len);
    S.row0 = aux ? seg[lane * NCLS]      : 0.0f;
    S.r96  = aux ? seg[lane * NCLS + 96] : -INFINITY;

    if (len == 8) {
        #pragma unroll
        for (int r = 0; r < 8; r++) {
            const float* row = seg + r * NCLS;
            S.a[r] = row[lane];
            S.b[r] = row[lane + 32];
            S.c[r] = row[lane + 64];
        }
    } else {
        #pragma unroll
        for (int r = 0; r < 8; r++) {
            const float* row = seg + r * NCLS;
            bool ok = (r < len);
            S.a[r] = ok ? row[lane]      : -INFINITY;
            S.b[r] = ok ? row[lane + 32] : -INFINITY;
            S.c[r] = ok ? row[lane + 64] : -INFINITY;
        }
    }
}

// Returns this segment's contribution (nonzero on lane 0 only).
__device__ __forceinline__ float compute_seg(const Seg& S, int lane,
                                             float invE, float invN)
{
    float lab0 = (lane == 0) ? 0.0f : S.lab0;       // reference: labels[:,0]=0
    const float lab1 = S.lab1, lab2 = S.lab2, lab96 = S.lab96;
    const int len = S.len;

    // n_mask bias folded into exp argument: 0 keeps, -INF kills.
    const float nb0 = (lab0  == 0.0f) ? 0.0f : -INFINITY;
    const float nb1 = (lab1  == 0.0f) ? 0.0f : -INFINITY;
    const float nb2 = (lab2  == 0.0f) ? 0.0f : -INFINITY;
    const float nb3 = (lab96 == 0.0f) ? 0.0f : -INFINITY;

    // Column maxima (segment_max) + per-row masked exp sums.
    float cm0 = S.a[0], cm1 = S.b[0], cm2 = S.c[0];
    float t[8];
    t[0] = ex2a(fmaf(S.a[0], LOG2E, nb0)) + ex2a(fmaf(S.b[0], LOG2E, nb1))
         + ex2a(fmaf(S.c[0], LOG2E, nb2));
    #pragma unroll
    for (int r = 1; r < 8; r++) {
        cm0 = fmaxf(cm0, S.a[r]); cm1 = fmaxf(cm1, S.b[r]); cm2 = fmaxf(cm2, S.c[r]);
        t[r] = ex2a(fmaf(S.a[r], LOG2E, nb0)) + ex2a(fmaf(S.b[r], LOG2E, nb1))
             + ex2a(fmaf(S.c[r], LOG2E, nb2));
    }

    // 8 interleaved butterfly sums (totals broadcast to all lanes).
    #pragma unroll
    for (int o = 16; o; o >>= 1) {
        #pragma unroll
        for (int r = 0; r < 8; r++)
            t[r] += __shfl_xor_sync(0xFFFFFFFFu, t[r], o);
    }

    // Lane r finishes row r: add its col-96 term, one batched log.
    float sel = t[0];
    #pragma unroll
    for (int r = 1; r < 8; r++) sel = (lane == r) ? t[r] : sel;
    const bool aux = (lane < len);
    float e96  = ex2a(fmaf(S.r96, LOG2E, nb3));     // 0 for lanes >= len
    float logv = __logf(sel + e96);                 // 8 logs, 1 MUFU slot
    float l2   = aux ? (logv - S.row0) : 0.0f;

    // Col-96 segment max (butterfly over lanes 0..7; -INF padding).
    float m96 = S.r96;
    #pragma unroll
    for (int o = 4; o; o >>= 1) m96 = fmaxf(m96, __shfl_xor_sync(0xFFFFFFFFu, m96, o));

    // loss1 lane terms (p_mask bias folded into exp args).
    bool p0 = (lab0 != 0.0f) || (lane == 0);
    const float pb0 = p0 ? 0.0f : -INFINITY;
    const float pb1 = (lab1 != 0.0f) ? 0.0f : -INFINITY;
    const float pb2 = (lab2 != 0.0f) ? 0.0f : -INFINITY;
    float S1   = ex2a(fmaf(cm0, LOG2E, pb0))
               + ex2a(fmaf(cm1, LOG2E, pb1))
               + ex2a(fmaf(cm2, LOG2E, pb2));
    float npos = lab0 + lab1 + lab2;
    float psum = lab0 * cm0 + lab1 * cm1 + lab2 * cm2;
    if (lane == 0 && lab96 != 0.0f) {
        S1   += ex2a(m96 * LOG2E);
        npos += lab96;
        psum += lab96 * m96;
    }

    // Single combined warp reduction of the 4 quantities.
    #pragma unroll
    for (int o = 16; o; o >>= 1) {
        S1   += __shfl_xor_sync(0xFFFFFFFFu, S1,   o);
        npos += __shfl_xor_sync(0xFFFFFFFFu, npos, o);
        psum += __shfl_xor_sync(0xFFFFFFFFu, psum, o);
        l2   += __shfl_xor_sync(0xFFFFFFFFu, l2,   o);
    }
    return (lane == 0) ? ((npos * __logf(S1) - psum) * invE + l2 * invN) : 0.0f;
}

__global__ __launch_bounds__(256, 3)
void atloss_kernel(const float* __restrict__ logits,
                   const float* __restrict__ labels,
                   const int*   __restrict__ pos,
                   int E, int N, float* __restrict__ out)
{
    __shared__ float s_part[8];
    const int lane = threadIdx.x & 31;
    const int wid  = threadIdx.x >> 5;
    const int GW   = gridDim.x * 8;                  // total warps
    const int gw   = blockIdx.x * 8 + wid;

    const float invE = 1.0f / (float)E;
    const float invN = 1.0f / (float)N;

    float acc = 0.0f;
    Seg A, B;
    int e = gw;
    if (e < E) {
        load_seg(A, logits, labels, pos, e, lane);
        for (;;) {
            // A is loaded for 'e'. Prefetch B, compute A.
            int eB = e + GW;
            bool vB = (eB < E);
            if (vB) load_seg(B, logits, labels, pos, eB, lane);
            acc += compute_seg(A, lane, invE, invN);
            if (!vB) break;
            // B is loaded for 'eB'. Prefetch A, compute B.
            int eA = eB + GW;
            bool vA = (eA < E);
            if (vA) load_seg(A, logits, labels, pos, eA, lane);
            acc += compute_seg(B, lane, invE, invN);
            if (!vA) break;
            e = eA;
        }
    }

    // ---- block fold + global atomic tail ----
    if (lane == 0) s_part[wid] = acc;
    __syncthreads();
    if (threadIdx.x == 0) {
        float bsum = 0.0f;
        #pragma unroll
        for (int w = 0; w < 8; w++) bsum += s_part[w];
        atomicAdd(&g_sum, (double)bsum);
        __threadfence();
        unsigned tkt = atomicAdd(&g_count, 1u);
        if (tkt == (unsigned)(gridDim.x - 1)) {
            double v = *((volatile double*)&g_sum);
            out[0] = (float)v;
            *((volatile double*)&g_sum) = 0.0;       // self-clean for next replay
            *((volatile unsigned*)&g_count) = 0u;
        }
    }
}

extern "C" void kernel_launch(void* const* d_in, const int* in_sizes, int n_in,
                              void* d_out, int out_size)
{
    const float* logits = (const float*)d_in[0];
    const float* labels = (const float*)d_in[1];
    const int*   pos    = (const int*)d_in[2];
    float* out = (float*)d_out;

    const int N = in_sizes[0] / NCLS;   // 524288
    const int E = in_sizes[1] / NCLS;   // 65536

    atloss_kernel<<<NBLK, 256>>>(logits, labels, pos, E, N, out);
}

// round 9
// speedup vs baseline: 1.4480x; 1.4480x over previous
#include <cuda_runtime.h>
#include <math.h>

#define NCLS 97
#define LOG2E 1.4426950408889634f
#define SEG_PER_WARP 4

// Final-accumulation state. Zero-initialized at module load; last block of each
// launch resets it, so graph replays always start from zero.
__device__ double   g_sum;
__device__ unsigned g_count;

__device__ __forceinline__ float ex2a(float x) {
    float y;
    asm("ex2.approx.ftz.f32 %0, %1;" : "=f"(y) : "f"(x));
    return y;   // ex2a(-INF) == 0
}

__global__ __launch_bounds__(256, 5)
void atloss_kernel(const float* __restrict__ logits,
                   const float* __restrict__ labels,
                   const int*   __restrict__ pos,
                   int E, int N, float* __restrict__ out)
{
    __shared__ float s_part[8];
    const int lane = threadIdx.x & 31;
    const int wid  = threadIdx.x >> 5;
    const int GW   = gridDim.x * 8;                 // total warps (16384)
    const float invE = 1.0f / (float)E;
    const float invN = 1.0f / (float)N;

    float acc = 0.0f;

    for (int e = blockIdx.x * 8 + wid; e < E; e += GW) {
        const int st  = __ldg(&pos[2 * e]);
        const int len = __ldg(&pos[2 * e + 1]) - st;          // == 8 here
        const float* seg = logits + (size_t)st * NCLS;
        const float* lab = labels + (size_t)e  * NCLS;

        // ---- labels (streamed): lane cols c0=lane, c1=lane+32, c2=lane+64 ----
        float lab0 = __ldcs(&lab[lane]); if (lane == 0) lab0 = 0.0f;  // labels[:,0]=0
        float lab1 = __ldcs(&lab[lane + 32]);
        float lab2 = __ldcs(&lab[lane + 64]);
        float lab96 = __ldcs(&lab[96]);
        // n_mask bias folded into exp argument: 0 keeps, -INF kills.
        const float nb0 = (lab0  == 0.0f) ? 0.0f : -INFINITY;
        const float nb1 = (lab1  == 0.0f) ? 0.0f : -INFINITY;
        const float nb2 = (lab2  == 0.0f) ? 0.0f : -INFINITY;
        const float nb3 = (lab96 == 0.0f) ? 0.0f : -INFINITY;

        // ---- per-lane auxiliary row data (lanes 0..len-1 own one row each) ----
        const bool aux = (lane < len);
        float row0_r = aux ? __ldcs(&seg[lane * NCLS])      : 0.0f;
        float r96    = aux ? __ldcs(&seg[lane * NCLS + 96]) : -INFINITY;

        // ---- row loads (streamed): unconditional fast path (len==8 here) ----
        float a[8], b[8], c[8];
        if (len == 8) {
            #pragma unroll
            for (int r = 0; r < 8; r++) {
                const float* row = seg + r * NCLS;
                a[r] = __ldcs(&row[lane]);
                b[r] = __ldcs(&row[lane + 32]);
                c[r] = __ldcs(&row[lane + 64]);
            }
        } else {
            #pragma unroll
            for (int r = 0; r < 8; r++) {
                const float* row = seg + r * NCLS;
                bool ok = (r < len);
                a[r] = ok ? __ldcs(&row[lane])      : -INFINITY;
                b[r] = ok ? __ldcs(&row[lane + 32]) : -INFINITY;
                c[r] = ok ? __ldcs(&row[lane + 64]) : -INFINITY;
            }
        }

        // ---- column maxima (segment_max) + per-row masked exp sums ----
        float cm0 = a[0], cm1 = b[0], cm2 = c[0];
        float t[8];
        t[0] = ex2a(fmaf(a[0], LOG2E, nb0)) + ex2a(fmaf(b[0], LOG2E, nb1))
             + ex2a(fmaf(c[0], LOG2E, nb2));
        #pragma unroll
        for (int r = 1; r < 8; r++) {
            cm0 = fmaxf(cm0, a[r]); cm1 = fmaxf(cm1, b[r]); cm2 = fmaxf(cm2, c[r]);
            t[r] = ex2a(fmaf(a[r], LOG2E, nb0)) + ex2a(fmaf(b[r], LOG2E, nb1))
                 + ex2a(fmaf(c[r], LOG2E, nb2));
        }

        // ---- 8 interleaved butterfly sums (totals broadcast to all lanes) ----
        #pragma unroll
        for (int o = 16; o; o >>= 1) {
            #pragma unroll
            for (int r = 0; r < 8; r++)
                t[r] += __shfl_xor_sync(0xFFFFFFFFu, t[r], o);
        }

        // ---- lane r finishes row r: add its col-96 term, one batched log ----
        float sel = t[0];
        #pragma unroll
        for (int r = 1; r < 8; r++) sel = (lane == r) ? t[r] : sel;
        float e96  = ex2a(fmaf(r96, LOG2E, nb3));            // 0 for lanes >= len
        float logv = __logf(sel + e96);                      // 8 logs, 1 MUFU slot
        float l2   = aux ? (logv - row0_r) : 0.0f;

        // ---- col-96 segment max (butterfly over lanes 0..7; -INF padding) ----
        float m96 = r96;
        #pragma unroll
        for (int o = 4; o; o >>= 1) m96 = fmaxf(m96, __shfl_xor_sync(0xFFFFFFFFu, m96, o));

        // ---- loss1 lane terms (p_mask bias folded into exp args) ----
        bool p0 = (lab0 != 0.0f) || (lane == 0);
        const float pb0 = p0 ? 0.0f : -INFINITY;
        const float pb1 = (lab1 != 0.0f) ? 0.0f : -INFINITY;
        const float pb2 = (lab2 != 0.0f) ? 0.0f : -INFINITY;
        float S1   = ex2a(fmaf(cm0, LOG2E, pb0))
                   + ex2a(fmaf(cm1, LOG2E, pb1))
                   + ex2a(fmaf(cm2, LOG2E, pb2));
        float npos = lab0 + lab1 + lab2;
        float psum = lab0 * cm0 + lab1 * cm1 + lab2 * cm2;
        if (lane == 0 && lab96 != 0.0f) {
            S1   += ex2a(m96 * LOG2E);
            npos += lab96;
            psum += lab96 * m96;
        }

        // ---- single combined warp reduction of the 4 quantities ----
        #pragma unroll
        for (int o = 16; o; o >>= 1) {
            S1   += __shfl_xor_sync(0xFFFFFFFFu, S1,   o);
            npos += __shfl_xor_sync(0xFFFFFFFFu, npos, o);
            psum += __shfl_xor_sync(0xFFFFFFFFu, psum, o);
            l2   += __shfl_xor_sync(0xFFFFFFFFu, l2,   o);
        }
        if (lane == 0)
            acc += (npos * __logf(S1) - psum) * invE + l2 * invN;
    }

    // ---- block fold + global atomic tail ----
    if (lane == 0) s_part[wid] = acc;
    __syncthreads();
    if (threadIdx.x == 0) {
        float bsum = 0.0f;
        #pragma unroll
        for (int w = 0; w < 8; w++) bsum += s_part[w];
        atomicAdd(&g_sum, (double)bsum);
        __threadfence();
        unsigned tkt = atomicAdd(&g_count, 1u);
        if (tkt == (unsigned)(gridDim.x - 1)) {
            double v = *((volatile double*)&g_sum);
            out[0] = (float)v;
            *((volatile double*)&g_sum) = 0.0;     // self-clean for next replay
            *((volatile unsigned*)&g_count) = 0u;
        }
    }
}

extern "C" void kernel_launch(void* const* d_in, const int* in_sizes, int n_in,
                              void* d_out, int out_size)
{
    const float* logits = (const float*)d_in[0];
    const float* labels = (const float*)d_in[1];
    const int*   pos    = (const int*)d_in[2];
    float* out = (float*)d_out;

    const int N  = in_sizes[0] / NCLS;   // 524288
    const int E  = in_sizes[1] / NCLS;   // 65536
    // 4 segments per warp: E / (8 warps * SEG_PER_WARP) blocks.
    const int nb = (E + 8 * SEG_PER_WARP - 1) / (8 * SEG_PER_WARP);   // 2048

    atloss_kernel<<<nb, 256>>>(logits, labels, pos, E, N, out);
}

// round 10
// speedup vs baseline: 1.6069x; 1.1098x over previous
#include <cuda_runtime.h>
#include <math.h>

#define NCLS 97
#define LOG2E 1.4426950408889634f
#define SEG_PER_WARP 4

// Final-accumulation state. Zero-initialized at module load; last block of each
// launch resets it, so graph replays always start from zero.
__device__ double   g_sum;
__device__ unsigned g_count;

__device__ __forceinline__ float ex2a(float x) {
    float y;
    asm("ex2.approx.ftz.f32 %0, %1;" : "=f"(y) : "f"(x));
    return y;   // ex2a(-INF) == 0
}

__device__ __forceinline__ void pf_l2(const void* p) {
    asm volatile("prefetch.global.L2 [%0];" :: "l"(p));
}

__global__ __launch_bounds__(256, 5)
void atloss_kernel(const float* __restrict__ logits,
                   const float* __restrict__ labels,
                   const int*   __restrict__ pos,
                   int E, int N, float* __restrict__ out)
{
    __shared__ float s_part[8];
    const int lane = threadIdx.x & 31;
    const int wid  = threadIdx.x >> 5;
    const int GW   = gridDim.x * 8;                 // total warps (16384)
    const float invE = 1.0f / (float)E;
    const float invN = 1.0f / (float)N;

    float acc = 0.0f;

    for (int e = blockIdx.x * 8 + wid; e < E; e += GW) {
        const int st  = __ldg(&pos[2 * e]);
        const int len = __ldg(&pos[2 * e + 1]) - st;          // == 8 here
        const float* seg = logits + (size_t)st * NCLS;
        const float* lab = labels + (size_t)e  * NCLS;

        // ---- labels (streamed): lane cols c0=lane, c1=lane+32, c2=lane+64 ----
        float lab0 = __ldcs(&lab[lane]); if (lane == 0) lab0 = 0.0f;  // labels[:,0]=0
        float lab1 = __ldcs(&lab[lane + 32]);
        float lab2 = __ldcs(&lab[lane + 64]);
        float lab96 = __ldcs(&lab[96]);
        // n_mask bias folded into exp argument: 0 keeps, -INF kills.
        const float nb0 = (lab0  == 0.0f) ? 0.0f : -INFINITY;
        const float nb1 = (lab1  == 0.0f) ? 0.0f : -INFINITY;
        const float nb2 = (lab2  == 0.0f) ? 0.0f : -INFINITY;
        const float nb3 = (lab96 == 0.0f) ? 0.0f : -INFINITY;

        // ---- per-lane auxiliary row data (lanes 0..len-1 own one row each) ----
        const bool aux = (lane < len);
        float row0_r = aux ? __ldcs(&seg[lane * NCLS])      : 0.0f;
        float r96    = aux ? __ldcs(&seg[lane * NCLS + 96]) : -INFINITY;

        // ---- row loads (streamed): unconditional fast path (len==8 here) ----
        float a[8], b[8], c[8];
        if (len == 8) {
            #pragma unroll
            for (int r = 0; r < 8; r++) {
                const float* row = seg + r * NCLS;
                a[r] = __ldcs(&row[lane]);
                b[r] = __ldcs(&row[lane + 32]);
                c[r] = __ldcs(&row[lane + 64]);
            }
        } else {
            #pragma unroll
            for (int r = 0; r < 8; r++) {
                const float* row = seg + r * NCLS;
                bool ok = (r < len);
                a[r] = ok ? __ldcs(&row[lane])      : -INFINITY;
                b[r] = ok ? __ldcs(&row[lane + 32]) : -INFINITY;
                c[r] = ok ? __ldcs(&row[lane + 64]) : -INFINITY;
            }
        }

        // ---- L2 prefetch of NEXT segment (zero register cost) ----
        // Logits: 3104 B -> lanes 0..25 prefetch one 128B line each.
        // Labels:  388 B -> lanes 26..30 cover up to 5 lines (unaligned worst case).
        {
            int enx = e + GW;
            if (enx < E) {
                int stn = __ldg(&pos[2 * enx]);
                const float* nseg = logits + (size_t)stn * NCLS;
                const float* nlab = labels + (size_t)enx * NCLS;
                if (lane < 26)       pf_l2(nseg + lane * 32);
                else if (lane < 31)  pf_l2(nlab + (lane - 26) * 32);
            }
        }

        // ---- column maxima (segment_max) + per-row masked exp sums ----
        float cm0 = a[0], cm1 = b[0], cm2 = c[0];
        float t[8];
        t[0] = ex2a(fmaf(a[0], LOG2E, nb0)) + ex2a(fmaf(b[0], LOG2E, nb1))
             + ex2a(fmaf(c[0], LOG2E, nb2));
        #pragma unroll
        for (int r = 1; r < 8; r++) {
            cm0 = fmaxf(cm0, a[r]); cm1 = fmaxf(cm1, b[r]); cm2 = fmaxf(cm2, c[r]);
            t[r] = ex2a(fmaf(a[r], LOG2E, nb0)) + ex2a(fmaf(b[r], LOG2E, nb1))
                 + ex2a(fmaf(c[r], LOG2E, nb2));
        }

        // ---- 8 interleaved butterfly sums (totals broadcast to all lanes) ----
        #pragma unroll
        for (int o = 16; o; o >>= 1) {
            #pragma unroll
            for (int r = 0; r < 8; r++)
                t[r] += __shfl_xor_sync(0xFFFFFFFFu, t[r], o);
        }

        // ---- lane r finishes row r: add its col-96 term, one batched log ----
        float sel = t[0];
        #pragma unroll
        for (int r = 1; r < 8; r++) sel = (lane == r) ? t[r] : sel;
        float e96  = ex2a(fmaf(r96, LOG2E, nb3));            // 0 for lanes >= len
        float logv = __logf(sel + e96);                      // 8 logs, 1 MUFU slot
        float l2   = aux ? (logv - row0_r) : 0.0f;

        // ---- col-96 segment max (butterfly over lanes 0..7; -INF padding) ----
        float m96 = r96;
        #pragma unroll
        for (int o = 4; o; o >>= 1) m96 = fmaxf(m96, __shfl_xor_sync(0xFFFFFFFFu, m96, o));

        // ---- loss1 lane terms (p_mask bias folded into exp args) ----
        bool p0 = (lab0 != 0.0f) || (lane == 0);
        const float pb0 = p0 ? 0.0f : -INFINITY;
        const float pb1 = (lab1 != 0.0f) ? 0.0f : -INFINITY;
        const float pb2 = (lab2 != 0.0f) ? 0.0f : -INFINITY;
        float S1   = ex2a(fmaf(cm0, LOG2E, pb0))
                   + ex2a(fmaf(cm1, LOG2E, pb1))
                   + ex2a(fmaf(cm2, LOG2E, pb2));
        float npos = lab0 + lab1 + lab2;
        float psum = lab0 * cm0 + lab1 * cm1 + lab2 * cm2;
        if (lane == 0 && lab96 != 0.0f) {
            S1   += ex2a(m96 * LOG2E);
            npos += lab96;
            psum += lab96 * m96;
        }

        // ---- single combined warp reduction of the 4 quantities ----
        #pragma unroll
        for (int o = 16; o; o >>= 1) {
            S1   += __shfl_xor_sync(0xFFFFFFFFu, S1,   o);
            npos += __shfl_xor_sync(0xFFFFFFFFu, npos, o);
            psum += __shfl_xor_sync(0xFFFFFFFFu, psum, o);
            l2   += __shfl_xor_sync(0xFFFFFFFFu, l2,   o);
        }
        if (lane == 0)
            acc += (npos * __logf(S1) - psum) * invE + l2 * invN;
    }

    // ---- block fold + global atomic tail ----
    if (lane == 0) s_part[wid] = acc;
    __syncthreads();
    if (threadIdx.x == 0) {
        float bsum = 0.0f;
        #pragma unroll
        for (int w = 0; w < 8; w++) bsum += s_part[w];
        atomicAdd(&g_sum, (double)bsum);
        __threadfence();
        unsigned tkt = atomicAdd(&g_count, 1u);
        if (tkt == (unsigned)(gridDim.x - 1)) {
            double v = *((volatile double*)&g_sum);
            out[0] = (float)v;
            *((volatile double*)&g_sum) = 0.0;     // self-clean for next replay
            *((volatile unsigned*)&g_count) = 0u;
        }
    }
}

extern "C" void kernel_launch(void* const* d_in, const int* in_sizes, int n_in,
                              void* d_out, int out_size)
{
    const float* logits = (const float*)d_in[0];
    const float* labels = (const float*)d_in[1];
    const int*   pos    = (const int*)d_in[2];
    float* out = (float*)d_out;

    const int N  = in_sizes[0] / NCLS;   // 524288
    const int E  = in_sizes[1] / NCLS;   // 65536
    // 4 segments per warp: E / (8 warps * SEG_PER_WARP) blocks.
    const int nb = (E + 8 * SEG_PER_WARP - 1) / (8 * SEG_PER_WARP);   // 2048

    atloss_kernel<<<nb, 256>>>(logits, labels, pos, E, N, out);
}

// round 11
// speedup vs baseline: 1.9163x; 1.1925x over previous
#include <cuda_runtime.h>
#include <math.h>

#define NCLS 97
#define LOG2E 1.4426950408889634f
#define NBLK 760   // 152 SMs x 5 resident blocks -> single persistent wave

// Final-accumulation state. Zero-initialized at module load; last block of each
// launch resets it, so graph replays always start from zero.
__device__ double   g_sum;
__device__ unsigned g_count;

__device__ __forceinline__ float ex2a(float x) {
    float y;
    asm("ex2.approx.ftz.f32 %0, %1;" : "=f"(y) : "f"(x));
    return y;   // ex2a(-INF) == 0
}

__device__ __forceinline__ void pf_l2(const void* p) {
    asm volatile("prefetch.global.L2 [%0];" :: "l"(p));
}

__global__ __launch_bounds__(256, 5)
void atloss_kernel(const float* __restrict__ logits,
                   const float* __restrict__ labels,
                   const int*   __restrict__ pos,
                   int E, int N, float* __restrict__ out)
{
    __shared__ float s_part[8];
    const int lane = threadIdx.x & 31;
    const int wid  = threadIdx.x >> 5;
    const int GW   = gridDim.x * 8;                 // total warps (6080)
    const float invE = 1.0f / (float)E;
    const float invN = 1.0f / (float)N;

    const bool b0 = (lane & 1);
    const bool b1 = (lane & 2);
    const bool b2 = (lane & 4);

    float acc = 0.0f;

    for (int e = blockIdx.x * 8 + wid; e < E; e += GW) {
        const int st  = __ldg(&pos[2 * e]);
        const int len = __ldg(&pos[2 * e + 1]) - st;          // == 8 here
        const float* seg = logits + (size_t)st * NCLS;
        const float* lab = labels + (size_t)e  * NCLS;

        // ---- labels (streamed): lane cols c0=lane, c1=lane+32, c2=lane+64 ----
        float lab0 = __ldcs(&lab[lane]); if (lane == 0) lab0 = 0.0f;  // labels[:,0]=0
        float lab1 = __ldcs(&lab[lane + 32]);
        float lab2 = __ldcs(&lab[lane + 64]);
        float lab96 = __ldcs(&lab[96]);
        // n_mask bias folded into exp argument: 0 keeps, -INF kills.
        const float nb0 = (lab0  == 0.0f) ? 0.0f : -INFINITY;
        const float nb1 = (lab1  == 0.0f) ? 0.0f : -INFINITY;
        const float nb2 = (lab2  == 0.0f) ? 0.0f : -INFINITY;
        const float nb3 = (lab96 == 0.0f) ? 0.0f : -INFINITY;

        // ---- per-lane auxiliary row data (lanes 0..len-1 own one row each) ----
        const bool aux = (lane < len);
        float row0_r = aux ? __ldcs(&seg[lane * NCLS])      : 0.0f;
        float r96    = aux ? __ldcs(&seg[lane * NCLS + 96]) : -INFINITY;

        // ---- row loads (streamed): unconditional fast path (len==8 here) ----
        float a[8], b[8], c[8];
        if (len == 8) {
            #pragma unroll
            for (int r = 0; r < 8; r++) {
                const float* row = seg + r * NCLS;
                a[r] = __ldcs(&row[lane]);
                b[r] = __ldcs(&row[lane + 32]);
                c[r] = __ldcs(&row[lane + 64]);
            }
        } else {
            #pragma unroll
            for (int r = 0; r < 8; r++) {
                const float* row = seg + r * NCLS;
                bool ok = (r < len);
                a[r] = ok ? __ldcs(&row[lane])      : -INFINITY;
                b[r] = ok ? __ldcs(&row[lane + 32]) : -INFINITY;
                c[r] = ok ? __ldcs(&row[lane + 64]) : -INFINITY;
            }
        }

        // ---- L2 prefetch of NEXT segment (zero register cost) ----
        {
            int enx = e + GW;
            if (enx < E) {
                int stn = __ldg(&pos[2 * enx]);
                const float* nseg = logits + (size_t)stn * NCLS;
                const float* nlab = labels + (size_t)enx * NCLS;
                if (lane < 26)       pf_l2(nseg + lane * 32);
                else if (lane < 31)  pf_l2(nlab + (lane - 26) * 32);
            }
        }

        // ---- column maxima (segment_max) + per-row masked exp sums ----
        float cm0 = a[0], cm1 = b[0], cm2 = c[0];
        float t[8];
        t[0] = ex2a(fmaf(a[0], LOG2E, nb0)) + ex2a(fmaf(b[0], LOG2E, nb1))
             + ex2a(fmaf(c[0], LOG2E, nb2));
        #pragma unroll
        for (int r = 1; r < 8; r++) {
            cm0 = fmaxf(cm0, a[r]); cm1 = fmaxf(cm1, b[r]); cm2 = fmaxf(cm2, c[r]);
            t[r] = ex2a(fmaf(a[r], LOG2E, nb0)) + ex2a(fmaf(b[r], LOG2E, nb1))
                 + ex2a(fmaf(c[r], LOG2E, nb2));
        }

        // ---- multi-value fold: 9 shuffles reduce 8 sums; lane r ends with T[r] ----
        // Stage 1 (value bit0 <- lane bit0):
        float u0 = b0 ? t[1] : t[0], q0 = b0 ? t[0] : t[1];
        float u1 = b0 ? t[3] : t[2], q1 = b0 ? t[2] : t[3];
        float u2 = b0 ? t[5] : t[4], q2 = b0 ? t[4] : t[5];
        float u3 = b0 ? t[7] : t[6], q3 = b0 ? t[6] : t[7];
        u0 += __shfl_xor_sync(0xFFFFFFFFu, q0, 1);
        u1 += __shfl_xor_sync(0xFFFFFFFFu, q1, 1);
        u2 += __shfl_xor_sync(0xFFFFFFFFu, q2, 1);
        u3 += __shfl_xor_sync(0xFFFFFFFFu, q3, 1);
        // Stage 2 (value bit1 <- lane bit1):
        float w0 = b1 ? u1 : u0, x0 = b1 ? u0 : u1;
        float w1 = b1 ? u3 : u2, x1 = b1 ? u2 : u3;
        w0 += __shfl_xor_sync(0xFFFFFFFFu, x0, 2);
        w1 += __shfl_xor_sync(0xFFFFFFFFu, x1, 2);
        // Stage 3 (value bit2 <- lane bit2):
        float y = b2 ? w1 : w0, z = b2 ? w0 : w1;
        y += __shfl_xor_sync(0xFFFFFFFFu, z, 4);
        // Butterfly over remaining lane bits:
        y += __shfl_xor_sync(0xFFFFFFFFu, y, 8);
        y += __shfl_xor_sync(0xFFFFFFFFu, y, 16);
        // y on lane l == total row-sum T[l & 7].

        // ---- lane r finishes row r: add its col-96 term, one batched log ----
        float e96  = ex2a(fmaf(r96, LOG2E, nb3));            // 0 for lanes >= len
        float logv = __logf(y + e96);                        // 8 logs, 1 MUFU slot
        float l2   = aux ? (logv - row0_r) : 0.0f;

        // ---- col-96 segment max (butterfly over lanes 0..7; -INF padding) ----
        float m96 = r96;
        #pragma unroll
        for (int o = 4; o; o >>= 1) m96 = fmaxf(m96, __shfl_xor_sync(0xFFFFFFFFu, m96, o));

        // ---- loss1 lane terms (p_mask bias folded into exp args) ----
        bool p0m = (lab0 != 0.0f) || (lane == 0);
        const float pb0 = p0m ? 0.0f : -INFINITY;
        const float pb1 = (lab1 != 0.0f) ? 0.0f : -INFINITY;
        const float pb2 = (lab2 != 0.0f) ? 0.0f : -INFINITY;
        float S1   = ex2a(fmaf(cm0, LOG2E, pb0))
                   + ex2a(fmaf(cm1, LOG2E, pb1))
                   + ex2a(fmaf(cm2, LOG2E, pb2));
        float npos = lab0 + lab1 + lab2;
        float psum = lab0 * cm0 + lab1 * cm1 + lab2 * cm2;
        if (lane == 0 && lab96 != 0.0f) {
            S1   += ex2a(m96 * LOG2E);
            npos += lab96;
            psum += lab96 * m96;
        }

        // ---- 4-value fold: lane l&3 ends with total of value (l&3) ----
        // values: 0=S1, 1=npos, 2=psum, 3=l2
        float p0v = b0 ? npos : S1,  g0 = b0 ? S1   : npos;
        float p1v = b0 ? l2   : psum, g1 = b0 ? psum : l2;
        p0v += __shfl_xor_sync(0xFFFFFFFFu, g0, 1);
        p1v += __shfl_xor_sync(0xFFFFFFFFu, g1, 1);
        float r0v = b1 ? p1v : p0v, h0 = b1 ? p0v : p1v;
        r0v += __shfl_xor_sync(0xFFFFFFFFu, h0, 2);
        r0v += __shfl_xor_sync(0xFFFFFFFFu, r0v, 4);
        r0v += __shfl_xor_sync(0xFFFFFFFFu, r0v, 8);
        r0v += __shfl_xor_sync(0xFFFFFFFFu, r0v, 16);
        // Gather totals to every lane (only lane 0 consumes):
        float S1t   = __shfl_sync(0xFFFFFFFFu, r0v, 0);
        float npost = __shfl_sync(0xFFFFFFFFu, r0v, 1);
        float psumt = __shfl_sync(0xFFFFFFFFu, r0v, 2);
        float l2t   = __shfl_sync(0xFFFFFFFFu, r0v, 3);
        if (lane == 0)
            acc += (npost * __logf(S1t) - psumt) * invE + l2t * invN;
    }

    // ---- block fold + global atomic tail ----
    if (lane == 0) s_part[wid] = acc;
    __syncthreads();
    if (threadIdx.x == 0) {
        float bsum = 0.0f;
        #pragma unroll
        for (int w = 0; w < 8; w++) bsum += s_part[w];
        atomicAdd(&g_sum, (double)bsum);
        __threadfence();
        unsigned tkt = atomicAdd(&g_count, 1u);
        if (tkt == (unsigned)(gridDim.x - 1)) {
            double v = *((volatile double*)&g_sum);
            out[0] = (float)v;
            *((volatile double*)&g_sum) = 0.0;     // self-clean for next replay
            *((volatile unsigned*)&g_count) = 0u;
        }
    }
}

extern "C" void kernel_launch(void* const* d_in, const int* in_sizes, int n_in,
                              void* d_out, int out_size)
{
    const float* logits = (const float*)d_in[0];
    const float* labels = (const float*)d_in[1];
    const int*   pos    = (const int*)d_in[2];
    float* out = (float*)d_out;

    const int N = in_sizes[0] / NCLS;   // 524288
    const int E = in_sizes[1] / NCLS;   // 65536

    atloss_kernel<<<NBLK, 256>>>(logits, labels, pos, E, N, out);
}